// round 8
// baseline (speedup 1.0000x reference)
#include <cuda_runtime.h>
#include <cstdint>

#define LL    320
#define DD    128
#define NBINS 32
#define EPSF  1e-8f

#define Z_ELEMS (LL*LL*DD)     // 13,107,200
#define P_ELEMS (3*LL*LL)      //    307,200
// output layout: [z | pxyz | cadistavg], all f32

// ---- z+p stream kernel
#define ZB      3200                    // z blocks: 3200*256*4 f4 = 3,276,800 = Z_ELEMS/4
#define PB      300                     // p blocks: 300*256 f4 = 76,800 = P_ELEMS/4
#define ZUNROLL 4

// ---- cadistavg kernel: 16x16 tiles, upper triangle (symmetric)
#define NT 20
#define C_BLOCKS 210                    // NT*(NT+1)/2
#define CH 16

__device__ __forceinline__ float fsqrt_approx(float x) {
    float y;
    asm("sqrt.approx.f32 %0, %1;" : "=f"(y) : "f"(x));
    return y;
}

__device__ __forceinline__ float dist3(float4 a, float4 b) {
    float dx = a.x - b.x, dy = a.y - b.y, dz = a.z - b.z;
    return fsqrt_approx(fmaf(dx, dx, fmaf(dy, dy, fmaf(dz, dz, EPSF))));
}

// ============ kernel 1: z = pair_feats + emb[idx]  (flat stream) + pxyz ============
__global__ void zp_kernel(const int* __restrict__ residx,
                          const int* __restrict__ mask,      // bool as int32
                          const float* __restrict__ emb,
                          const float4* __restrict__ pair4,
                          const float4* __restrict__ pred4,
                          const float4* __restrict__ md4,
                          float* __restrict__ out)
{
    const int blk = blockIdx.x;
    const int tid = threadIdx.x;

    if (blk < ZB) {
        const float4* e4 = (const float4*)emb;
        float4* out4 = (float4*)out;
        const int stride = ZB * 256;
        int e = blk * 256 + tid;                 // float4 index into z
        #pragma unroll
        for (int k = 0; k < ZUNROLL; k++, e += stride) {
            const int p = e >> 5;                // pair index (32 f4 per pair)
            const int s = e & 31;                // f4 slot within D=128
            const int i = p / LL;
            const int j = p - i * LL;

            int m   = mask[i] & mask[j];
            int dif = residx[j] - residx[i];
            dif = min(max(dif, -NBINS), NBINS) + (NBINS + 1);
            const int idx = m ? dif : 0;

            float4 ev = e4[idx * (DD / 4) + s];
            float4 pv = pair4[e];
            out4[e] = make_float4(pv.x + ev.x, pv.y + ev.y,
                                  pv.z + ev.z, pv.w + ev.w);
        }
    } else {
        // pxyz = predxyz * maskdiag
        const int e = (blk - ZB) * 256 + tid;    // < 76800
        float4 pv = pred4[e];
        float4 mv = md4[e % (LL * LL / 4)];
        ((float4*)(out + Z_ELEMS))[e] =
            make_float4(pv.x * mv.x, pv.y * mv.y, pv.z * mv.z, pv.w * mv.w);
    }
}

// ============ kernel 2: cadistavg (double-buffered smem, 1 barrier/chunk) ============
__global__ __launch_bounds__(256)
void c_kernel(const float* __restrict__ predxyz,
              const float* __restrict__ maskdiag,
              float* __restrict__ out)
{
    __shared__ float4 sK[2][CH][16];
    __shared__ float4 sJ[2][CH][16];

    const int blk = blockIdx.x;
    const int tid = threadIdx.x;

    // blk -> (a, b2), a <= b2
    int a = 0, t = blk;
    while (t >= NT - a) { t -= NT - a; a++; }
    const int b2 = a + t;
    const int jt = a * 16;
    const int kt = b2 * 16;

    const int tx = tid & 15;
    const int ty = tid >> 4;

    float kx, ky, kz, jx, jy, jz;
    // prefetch chunk 0
    {
        const int gi = ty;
        const int ck = kt + tx;
        const float mdk = maskdiag[gi * LL + ck];
        kx = predxyz[0 * LL * LL + gi * LL + ck] * mdk;
        ky = predxyz[1 * LL * LL + gi * LL + ck] * mdk;
        kz = predxyz[2 * LL * LL + gi * LL + ck] * mdk;
        const int cj = jt + tx;
        const float mdj = maskdiag[gi * LL + cj];
        jx = predxyz[0 * LL * LL + gi * LL + cj] * mdj;
        jy = predxyz[1 * LL * LL + gi * LL + cj] * mdj;
        jz = predxyz[2 * LL * LL + gi * LL + cj] * mdj;
    }
    sK[0][ty][tx] = make_float4(kx, ky, kz, 0.f);
    sJ[0][ty][tx] = make_float4(jx, jy, jz, 0.f);

    float acc0 = 0.f, acc1 = 0.f, acc2 = 0.f, acc3 = 0.f;

    #pragma unroll 1
    for (int c = 0; c < LL / CH; c++) {
        const int cur = c & 1;
        __syncthreads();                       // buf[cur] fully stored
        if (c + 1 < LL / CH) {                 // prefetch next chunk into regs
            const int gi = (c + 1) * CH + ty;
            const int ck = kt + tx;
            const float mdk = maskdiag[gi * LL + ck];
            kx = predxyz[0 * LL * LL + gi * LL + ck] * mdk;
            ky = predxyz[1 * LL * LL + gi * LL + ck] * mdk;
            kz = predxyz[2 * LL * LL + gi * LL + ck] * mdk;
            const int cj = jt + tx;
            const float mdj = maskdiag[gi * LL + cj];
            jx = predxyz[0 * LL * LL + gi * LL + cj] * mdj;
            jy = predxyz[1 * LL * LL + gi * LL + cj] * mdj;
            jz = predxyz[2 * LL * LL + gi * LL + cj] * mdj;
        }
        #pragma unroll
        for (int ii = 0; ii < CH; ii += 4) {
            acc0 += dist3(sK[cur][ii + 0][tx], sJ[cur][ii + 0][ty]);
            acc1 += dist3(sK[cur][ii + 1][tx], sJ[cur][ii + 1][ty]);
            acc2 += dist3(sK[cur][ii + 2][tx], sJ[cur][ii + 2][ty]);
            acc3 += dist3(sK[cur][ii + 3][tx], sJ[cur][ii + 3][ty]);
        }
        if (c + 1 < LL / CH) {                 // store into the other buffer
            sK[cur ^ 1][ty][tx] = make_float4(kx, ky, kz, 0.f);
            sJ[cur ^ 1][ty][tx] = make_float4(jx, jy, jz, 0.f);
        }
    }

    float* cd = out + Z_ELEMS + P_ELEMS;
    const float v = (acc0 + acc1 + acc2 + acc3) * (1.0f / LL);
    cd[(jt + ty) * LL + (kt + tx)] = v;
    if (a != b2)
        cd[(kt + tx) * LL + (jt + ty)] = v;    // symmetric mirror
}

extern "C" void kernel_launch(void* const* d_in, const int* in_sizes, int n_in,
                              void* d_out, int out_size) {
    const int*    residx   = (const int*)d_in[0];
    const int*    mask     = (const int*)d_in[1];
    const float*  emb      = (const float*)d_in[2];
    const float4* pair4    = (const float4*)d_in[3];
    const float*  predxyz  = (const float*)d_in[4];
    const float*  maskdiag = (const float*)d_in[5];
    float*        out      = (float*)d_out;

    zp_kernel<<<ZB + PB, 256>>>(residx, mask, emb, pair4,
                                (const float4*)predxyz, (const float4*)maskdiag,
                                out);
    c_kernel<<<C_BLOCKS, 256>>>(predxyz, maskdiag, out);
}

// round 9
// speedup vs baseline: 1.1524x; 1.1524x over previous
#include <cuda_runtime.h>
#include <cstdint>

#define LL    320
#define DD    128
#define NBINS 32
#define EPSF  1e-8f

#define Z_ELEMS (LL*LL*DD)     // 13,107,200
#define P_ELEMS (3*LL*LL)      //    307,200
#define CD_ELEMS (LL*LL)       //    102,400
// output layout: [z | pxyz | cadistavg], all f32

// ---- z+p+zero kernel
#define ZB      3200                    // 3200*256*4 f4 = Z_ELEMS/4
#define PB      300                     // 300*256 f4 = P_ELEMS/4
#define CDZB    100                     // 100*256 f4 = CD_ELEMS/4 (zero-init)
#define ZUNROLL 4

// ---- cadistavg kernel: 16x16 tiles, upper triangle, i-split x4
#define NT 20
#define C_TILES 210                     // NT*(NT+1)/2
#define ICHUNKS 4
#define ISPAN  (LL/ICHUNKS)             // 80
#define C_BLOCKS (C_TILES*ICHUNKS)      // 840
#define CH 16

__device__ __forceinline__ float fsqrt_approx(float x) {
    float y;
    asm("sqrt.approx.f32 %0, %1;" : "=f"(y) : "f"(x));
    return y;
}

__device__ __forceinline__ float dist3(float4 a, float4 b) {
    float dx = a.x - b.x, dy = a.y - b.y, dz = a.z - b.z;
    return fsqrt_approx(fmaf(dx, dx, fmaf(dy, dy, fmaf(dz, dz, EPSF))));
}

// ============ kernel 1: z stream + pxyz + zero(cadistavg) ============
__global__ void zp_kernel(const int* __restrict__ residx,
                          const int* __restrict__ mask,      // bool as int32
                          const float* __restrict__ emb,
                          const float4* __restrict__ pair4,
                          const float4* __restrict__ pred4,
                          const float4* __restrict__ md4,
                          float* __restrict__ out)
{
    const int blk = blockIdx.x;
    const int tid = threadIdx.x;

    if (blk < ZB) {
        const float4* e4 = (const float4*)emb;
        float4* out4 = (float4*)out;
        const int stride = ZB * 256;
        int e = blk * 256 + tid;                 // float4 index into z
        #pragma unroll
        for (int k = 0; k < ZUNROLL; k++, e += stride) {
            const int p = e >> 5;                // pair index (32 f4 per pair)
            const int s = e & 31;                // f4 slot within D=128
            const int i = p / LL;
            const int j = p - i * LL;

            int m   = mask[i] & mask[j];
            int dif = residx[j] - residx[i];
            dif = min(max(dif, -NBINS), NBINS) + (NBINS + 1);
            const int idx = m ? dif : 0;

            float4 ev = e4[idx * (DD / 4) + s];
            float4 pv = pair4[e];
            out4[e] = make_float4(pv.x + ev.x, pv.y + ev.y,
                                  pv.z + ev.z, pv.w + ev.w);
        }
    } else if (blk < ZB + PB) {
        // pxyz = predxyz * maskdiag
        const int e = (blk - ZB) * 256 + tid;    // < 76800
        float4 pv = pred4[e];
        float4 mv = md4[e % (LL * LL / 4)];
        ((float4*)(out + Z_ELEMS))[e] =
            make_float4(pv.x * mv.x, pv.y * mv.y, pv.z * mv.z, pv.w * mv.w);
    } else {
        // zero-init cadistavg (accumulated by c_kernel via atomics)
        const int e = (blk - ZB - PB) * 256 + tid;   // < 25600
        ((float4*)(out + Z_ELEMS + P_ELEMS))[e] = make_float4(0.f, 0.f, 0.f, 0.f);
    }
}

// ============ kernel 2: cadistavg, 16x16 tile x i-chunk, atomic accumulate ============
__global__ __launch_bounds__(256)
void c_kernel(const float* __restrict__ predxyz,
              const float* __restrict__ maskdiag,
              float* __restrict__ out)
{
    __shared__ float4 sK[CH][16];
    __shared__ float4 sJ[CH][16];

    const int blk  = blockIdx.x;
    const int tid  = threadIdx.x;
    const int tile = blk >> 2;          // 0..209
    const int chnk = blk & 3;           // i-chunk 0..3

    // tile -> (a, b2), a <= b2
    int a = 0, t = tile;
    while (t >= NT - a) { t -= NT - a; a++; }
    const int b2 = a + t;
    const int jt = a * 16;
    const int kt = b2 * 16;

    const int tx = tid & 15;            // k within tile (staging col)
    const int ty = tid >> 4;            // j within tile (staging i-row)

    float acc0 = 0.f, acc1 = 0.f, acc2 = 0.f, acc3 = 0.f;

    const int i_beg = chnk * ISPAN;
    for (int i0 = i_beg; i0 < i_beg + ISPAN; i0 += CH) {
        const int gi = i0 + ty;
        {
            int col = kt + tx;
            float md = maskdiag[gi * LL + col];
            sK[ty][tx] = make_float4(
                predxyz[0 * LL * LL + gi * LL + col] * md,
                predxyz[1 * LL * LL + gi * LL + col] * md,
                predxyz[2 * LL * LL + gi * LL + col] * md, 0.f);
            col = jt + tx;
            md = maskdiag[gi * LL + col];
            sJ[ty][tx] = make_float4(
                predxyz[0 * LL * LL + gi * LL + col] * md,
                predxyz[1 * LL * LL + gi * LL + col] * md,
                predxyz[2 * LL * LL + gi * LL + col] * md, 0.f);
        }
        __syncthreads();
        #pragma unroll
        for (int ii = 0; ii < CH; ii += 4) {
            acc0 += dist3(sK[ii + 0][tx], sJ[ii + 0][ty]);
            acc1 += dist3(sK[ii + 1][tx], sJ[ii + 1][ty]);
            acc2 += dist3(sK[ii + 2][tx], sJ[ii + 2][ty]);
            acc3 += dist3(sK[ii + 3][tx], sJ[ii + 3][ty]);
        }
        __syncthreads();
    }

    float* cd = out + Z_ELEMS + P_ELEMS;
    const float v = (acc0 + acc1 + acc2 + acc3) * (1.0f / LL);
    atomicAdd(&cd[(jt + ty) * LL + (kt + tx)], v);
    if (a != b2)
        atomicAdd(&cd[(kt + tx) * LL + (jt + ty)], v);   // symmetric mirror
}

extern "C" void kernel_launch(void* const* d_in, const int* in_sizes, int n_in,
                              void* d_out, int out_size) {
    const int*    residx   = (const int*)d_in[0];
    const int*    mask     = (const int*)d_in[1];
    const float*  emb      = (const float*)d_in[2];
    const float4* pair4    = (const float4*)d_in[3];
    const float*  predxyz  = (const float*)d_in[4];
    const float*  maskdiag = (const float*)d_in[5];
    float*        out      = (float*)d_out;

    zp_kernel<<<ZB + PB + CDZB, 256>>>(residx, mask, emb, pair4,
                                       (const float4*)predxyz,
                                       (const float4*)maskdiag, out);
    c_kernel<<<C_BLOCKS, 256>>>(predxyz, maskdiag, out);
}

// round 10
// speedup vs baseline: 1.3992x; 1.2141x over previous
#include <cuda_runtime.h>
#include <cstdint>

#define LL    320
#define DD    128
#define NBINS 32
#define EPSF  1e-8f

#define Z_ELEMS (LL*LL*DD)     // 13,107,200
#define P_ELEMS (3*LL*LL)      //    307,200
#define CD_ELEMS (LL*LL)       //    102,400
// output layout: [z | pxyz | cadistavg], all f32

// ---- cadistavg: 32x32 tiles, upper triangle, i-split x8, 2x2 microtile
#define NT2 10                  // 320/32
#define C_TILES 55              // NT2*(NT2+1)/2
#define ICHUNKS 8
#define ISPAN  (LL/ICHUNKS)     // 40
#define C_BLOCKS (C_TILES*ICHUNKS)   // 440
#define CCH 8                   // i-rows staged per chunk

// ---- z / p stream
#define ZB 3200                 // 3200*256*4 f4 = Z_ELEMS/4
#define PB 300                  // 300*256 f4 = P_ELEMS/4
#define ZUNROLL 4

#define GRID1 (C_BLOCKS + ZB + PB)   // 3940

// per-chunk partial sums of cadistavg (reduced by kernel 2)
__device__ float g_cd_part[ICHUNKS * CD_ELEMS];   // 3.3 MB static scratch

__device__ __forceinline__ float fsqrt_approx(float x) {
    float y;
    asm("sqrt.approx.f32 %0, %1;" : "=f"(y) : "f"(x));
    return y;
}

__device__ __forceinline__ float dist3(float4 a, float4 b) {
    float dx = a.x - b.x, dy = a.y - b.y, dz = a.z - b.z;
    return fsqrt_approx(fmaf(dx, dx, fmaf(dy, dy, fmaf(dz, dz, EPSF))));
}

// ============ kernel 1: C partials (first) + z stream + pxyz ============
__global__ __launch_bounds__(256)
void fused1(const int* __restrict__ residx,
            const int* __restrict__ mask,        // bool as int32
            const float* __restrict__ emb,
            const float4* __restrict__ pair4,
            const float* __restrict__ predxyz,
            const float* __restrict__ maskdiag,
            float* __restrict__ out)
{
    const int blk = blockIdx.x;
    const int tid = threadIdx.x;

    if (blk < C_BLOCKS) {
        // ---- cadistavg partial: 32x32 (j,k) tile over one i-chunk of 40
        __shared__ float4 sK[CCH][32];
        __shared__ float4 sJ[CCH][32];

        const int tile = blk >> 3;          // 0..54
        const int chnk = blk & 7;           // i-chunk 0..7

        int a = 0, t = tile;                // tile -> (a, b2), a <= b2
        while (t >= NT2 - a) { t -= NT2 - a; a++; }
        const int b2 = a + t;
        const int jt = a * 32;
        const int kt = b2 * 32;

        // staging role: 128 threads per tile-side, float2 (2 cols) each
        const int side = tid >> 7;          // 0 = K cols, 1 = J cols
        const int rem  = tid & 127;
        const int sii  = rem >> 4;          // i-row within chunk (0..7)
        const int scol = (side ? jt : kt) + 2 * (rem & 15);

        // compute role: 2x2 microtile
        const int tx = tid & 15;            // k, k+16
        const int ty = tid >> 4;            // j, j+16

        float v00 = 0.f, v01 = 0.f, v10 = 0.f, v11 = 0.f;

        const int ibeg = chnk * ISPAN;
        for (int i0 = ibeg; i0 < ibeg + ISPAN; i0 += CCH) {
            const int gi = i0 + sii;
            const float2 px = *(const float2*)(predxyz + 0 * LL * LL + gi * LL + scol);
            const float2 py = *(const float2*)(predxyz + 1 * LL * LL + gi * LL + scol);
            const float2 pz = *(const float2*)(predxyz + 2 * LL * LL + gi * LL + scol);
            const float2 m2 = *(const float2*)(maskdiag + gi * LL + scol);

            __syncthreads();                // previous chunk's compute done
            {
                float4* dst = side ? &sJ[sii][scol - jt] : &sK[sii][scol - kt];
                dst[0] = make_float4(px.x * m2.x, py.x * m2.x, pz.x * m2.x, 0.f);
                dst[1] = make_float4(px.y * m2.y, py.y * m2.y, pz.y * m2.y, 0.f);
            }
            __syncthreads();                // chunk staged

            #pragma unroll
            for (int ii = 0; ii < CCH; ii++) {
                const float4 ka = sK[ii][tx];
                const float4 kb = sK[ii][tx + 16];
                const float4 ja = sJ[ii][ty];
                const float4 jb = sJ[ii][ty + 16];
                v00 += dist3(ka, ja);
                v01 += dist3(kb, ja);
                v10 += dist3(ka, jb);
                v11 += dist3(kb, jb);
            }
        }

        float* part = g_cd_part + chnk * CD_ELEMS;
        const float s = 1.0f / LL;
        part[(jt + ty)      * LL + kt + tx]      = v00 * s;
        part[(jt + ty)      * LL + kt + tx + 16] = v01 * s;
        part[(jt + ty + 16) * LL + kt + tx]      = v10 * s;
        part[(jt + ty + 16) * LL + kt + tx + 16] = v11 * s;
        if (a != b2) {                       // mirror (symmetric)
            part[(kt + tx)      * LL + jt + ty]      = v00 * s;
            part[(kt + tx + 16) * LL + jt + ty]      = v01 * s;
            part[(kt + tx)      * LL + jt + ty + 16] = v10 * s;
            part[(kt + tx + 16) * LL + jt + ty + 16] = v11 * s;
        }

    } else if (blk < C_BLOCKS + ZB) {
        // ---- z = pair_feats + emb[idx]
        const float4* e4 = (const float4*)emb;
        float4* out4 = (float4*)out;
        const int stride = ZB * 256;
        int e = (blk - C_BLOCKS) * 256 + tid;    // float4 index into z
        #pragma unroll
        for (int k = 0; k < ZUNROLL; k++, e += stride) {
            const int p = e >> 5;                // pair index (32 f4 per pair)
            const int s = e & 31;                // f4 slot within D=128
            const int i = p / LL;
            const int j = p - i * LL;

            int m   = mask[i] & mask[j];
            int dif = residx[j] - residx[i];
            dif = min(max(dif, -NBINS), NBINS) + (NBINS + 1);
            const int idx = m ? dif : 0;

            float4 ev = e4[idx * (DD / 4) + s];
            float4 pv = pair4[e];
            out4[e] = make_float4(pv.x + ev.x, pv.y + ev.y,
                                  pv.z + ev.z, pv.w + ev.w);
        }
    } else {
        // ---- pxyz = predxyz * maskdiag
        const int e = (blk - C_BLOCKS - ZB) * 256 + tid;   // < 76800
        const float4* pr4 = (const float4*)predxyz;
        const float4* md4 = (const float4*)maskdiag;
        float4 pv = pr4[e];
        float4 mv = md4[e % (LL * LL / 4)];
        ((float4*)(out + Z_ELEMS))[e] =
            make_float4(pv.x * mv.x, pv.y * mv.y, pv.z * mv.z, pv.w * mv.w);
    }
}

// ============ kernel 2: reduce the 8 chunk partials into cadistavg ============
__global__ __launch_bounds__(256)
void cd_reduce(float* __restrict__ out)
{
    const int e = blockIdx.x * 256 + threadIdx.x;   // < 102400
    float s = 0.f;
    #pragma unroll
    for (int c = 0; c < ICHUNKS; c++)
        s += g_cd_part[c * CD_ELEMS + e];
    out[Z_ELEMS + P_ELEMS + e] = s;
}

extern "C" void kernel_launch(void* const* d_in, const int* in_sizes, int n_in,
                              void* d_out, int out_size) {
    const int*    residx   = (const int*)d_in[0];
    const int*    mask     = (const int*)d_in[1];
    const float*  emb      = (const float*)d_in[2];
    const float4* pair4    = (const float4*)d_in[3];
    const float*  predxyz  = (const float*)d_in[4];
    const float*  maskdiag = (const float*)d_in[5];
    float*        out      = (float*)d_out;

    fused1<<<GRID1, 256>>>(residx, mask, emb, pair4, predxyz, maskdiag, out);
    cd_reduce<<<CD_ELEMS / 256, 256>>>(out);
}